// round 1
// baseline (speedup 1.0000x reference)
#include <cuda_runtime.h>
#include <cuda_bf16.h>

// Problem constants
#define BB    2048
#define TT    200
#define DD    64
#define H1    256
#define H2    128
#define H3    64
#define NTOK  (BB * TT)          // 409600

#define TOK_PER_WARP 8
#define WARPS_PER_CTA 4
#define TOK_PER_CTA (TOK_PER_WARP * WARPS_PER_CTA)   // 32
#define NBLK (NTOK / TOK_PER_CTA)                     // 12800 (exact)

// Scratch (allocation-free rule: __device__ globals)
__device__ float g_qproj[BB * H1];     // q @ (W1a + W1c) + b1, per batch  (2 MB)
__device__ float g_W1bp[DD * H1];      // folded k-weights: W1b - W1c      (64 KB)

// ---------------------------------------------------------------------------
// Prep kernel 1: fold W1 rows [64:128] - [128:192] -> g_W1bp
// ---------------------------------------------------------------------------
__global__ void fold_w1_kernel(const float* __restrict__ W1) {
    int i = blockIdx.x * blockDim.x + threadIdx.x;
    if (i < DD * H1) {
        int kk = i / H1, n = i % H1;
        g_W1bp[i] = W1[(DD + kk) * H1 + n] - W1[(2 * DD + kk) * H1 + n];
    }
}

// ---------------------------------------------------------------------------
// Prep kernel 2: g_qproj[b][n] = b1[n] + sum_i q[b][i] * (W1[i][n] + W1[128+i][n])
// grid = BB blocks of H1 threads
// ---------------------------------------------------------------------------
__global__ void qproj_kernel(const float* __restrict__ q,
                             const float* __restrict__ W1,
                             const float* __restrict__ b1) {
    __shared__ float qs[DD];
    int b = blockIdx.x;
    int n = threadIdx.x;
    if (n < DD) qs[n] = q[b * DD + n];
    __syncthreads();
    float acc = b1[n];
#pragma unroll 8
    for (int i = 0; i < DD; i++) {
        acc = fmaf(qs[i], W1[i * H1 + n] + W1[(2 * DD + i) * H1 + n], acc);
    }
    g_qproj[b * H1 + n] = acc;
}

// ---------------------------------------------------------------------------
// Main fused kernel.
// CTA = 128 threads (4 warps), 32 tokens/CTA, 8 tokens/warp.
// Each warp owns its 8 tokens end-to-end (no cross-warp deps in hot path).
// Lane n-mapping: output column n = lane + 32*jj.
// Dynamic smem layout (floats): kv[32][64] | qk[32][64] | h1[32][256] | h2[32][128]
// ---------------------------------------------------------------------------
#define SMEM_FLOATS (32*64 + 32*64 + 32*256 + 32*128)   // 16384 floats = 64 KB

__global__ void __launch_bounds__(128, 3)
attn_pool_main(const float* __restrict__ q,
               const float* __restrict__ kten,
               const float* __restrict__ W1,
               const float* __restrict__ a1,
               const float* __restrict__ W2,
               const float* __restrict__ b2,
               const float* __restrict__ a2,
               const float* __restrict__ W3,
               const float* __restrict__ b3,
               const float* __restrict__ a3,
               const float* __restrict__ Wl,
               const float* __restrict__ bl,
               float* __restrict__ out) {
    extern __shared__ float smem[];
    float* kv_sm = smem;                    // [32][64]
    float* qk_sm = smem + 32 * 64;          // [32][64]
    float* h1_sm = smem + 2 * 32 * 64;      // [32][256]
    float* h2_sm = smem + 2 * 32 * 64 + 32 * 256; // [32][128]

    const int lane = threadIdx.x & 31;
    const int warp = threadIdx.x >> 5;
    const int m0   = warp * TOK_PER_WARP;              // token slot base in CTA
    const int tok0 = blockIdx.x * TOK_PER_CTA + m0;    // global token index base

    // ---------------- Load k, compute q*k (all tokens valid: NTOK % 32 == 0)
#pragma unroll
    for (int m = 0; m < TOK_PER_WARP; m++) {
        int idx = tok0 + m;
        int b   = idx / TT;
        float k0 = kten[idx * DD + lane];
        float k1 = kten[idx * DD + 32 + lane];
        float q0 = q[b * DD + lane];
        float q1 = q[b * DD + 32 + lane];
        kv_sm[(m0 + m) * DD + lane]      = k0;
        kv_sm[(m0 + m) * DD + 32 + lane] = k1;
        qk_sm[(m0 + m) * DD + lane]      = q0 * k0;
        qk_sm[(m0 + m) * DD + 32 + lane] = q1 * k1;
    }
    __syncwarp();

    // ---------------- Layer 1: h1 = PReLU(qproj + kv@W1bp + qk@W1d, a1)
    const float* W1d = W1 + 3 * DD * H1;   // rows [192:256]
    float acc1[TOK_PER_WARP][8];
#pragma unroll
    for (int m = 0; m < TOK_PER_WARP; m++) {
        int b = (tok0 + m) / TT;
#pragma unroll
        for (int jj = 0; jj < 8; jj++)
            acc1[m][jj] = g_qproj[b * H1 + lane + jj * 32];
    }
#pragma unroll 2
    for (int kk = 0; kk < DD; kk++) {
        float xk[TOK_PER_WARP];
#pragma unroll
        for (int m = 0; m < TOK_PER_WARP; m++) xk[m] = kv_sm[(m0 + m) * DD + kk];
#pragma unroll
        for (int jj = 0; jj < 8; jj++) {
            float w = g_W1bp[kk * H1 + lane + jj * 32];
#pragma unroll
            for (int m = 0; m < TOK_PER_WARP; m++)
                acc1[m][jj] = fmaf(xk[m], w, acc1[m][jj]);
        }
    }
#pragma unroll 2
    for (int kk = 0; kk < DD; kk++) {
        float xk[TOK_PER_WARP];
#pragma unroll
        for (int m = 0; m < TOK_PER_WARP; m++) xk[m] = qk_sm[(m0 + m) * DD + kk];
#pragma unroll
        for (int jj = 0; jj < 8; jj++) {
            float w = W1d[kk * H1 + lane + jj * 32];
#pragma unroll
            for (int m = 0; m < TOK_PER_WARP; m++)
                acc1[m][jj] = fmaf(xk[m], w, acc1[m][jj]);
        }
    }
#pragma unroll
    for (int m = 0; m < TOK_PER_WARP; m++) {
        int t = (tok0 + m) % TT;
#pragma unroll
        for (int jj = 0; jj < 8; jj++) {
            int n = lane + jj * 32;
            float v = acc1[m][jj];
            float al = a1[t * H1 + n];
            v = (v > 0.f) ? v : al * v;
            h1_sm[(m0 + m) * H1 + n] = v;
        }
    }
    __syncwarp();

    // ---------------- Layer 2: h2 = PReLU(h1 @ W2 + b2, a2)   K=256, N=128
    float acc2[TOK_PER_WARP][4];
    {
        float bb2[4];
#pragma unroll
        for (int jj = 0; jj < 4; jj++) bb2[jj] = b2[lane + jj * 32];
#pragma unroll
        for (int m = 0; m < TOK_PER_WARP; m++)
#pragma unroll
            for (int jj = 0; jj < 4; jj++) acc2[m][jj] = bb2[jj];
    }
#pragma unroll 2
    for (int kk = 0; kk < H1; kk++) {
        float xk[TOK_PER_WARP];
#pragma unroll
        for (int m = 0; m < TOK_PER_WARP; m++) xk[m] = h1_sm[(m0 + m) * H1 + kk];
#pragma unroll
        for (int jj = 0; jj < 4; jj++) {
            float w = W2[kk * H2 + lane + jj * 32];
#pragma unroll
            for (int m = 0; m < TOK_PER_WARP; m++)
                acc2[m][jj] = fmaf(xk[m], w, acc2[m][jj]);
        }
    }
#pragma unroll
    for (int m = 0; m < TOK_PER_WARP; m++) {
        int t = (tok0 + m) % TT;
#pragma unroll
        for (int jj = 0; jj < 4; jj++) {
            int n = lane + jj * 32;
            float v = acc2[m][jj];
            float al = a2[t * H2 + n];
            v = (v > 0.f) ? v : al * v;
            h2_sm[(m0 + m) * H2 + n] = v;
        }
    }
    __syncwarp();

    // ---------------- Layer 3: h3 = PReLU(h2 @ W3 + b3, a3)   K=128, N=64
    float acc3[TOK_PER_WARP][2];
    {
        float bb3[2];
        bb3[0] = b3[lane];
        bb3[1] = b3[lane + 32];
#pragma unroll
        for (int m = 0; m < TOK_PER_WARP; m++) {
            acc3[m][0] = bb3[0];
            acc3[m][1] = bb3[1];
        }
    }
#pragma unroll 2
    for (int kk = 0; kk < H2; kk++) {
        float xk[TOK_PER_WARP];
#pragma unroll
        for (int m = 0; m < TOK_PER_WARP; m++) xk[m] = h2_sm[(m0 + m) * H2 + kk];
        float w0 = W3[kk * H3 + lane];
        float w1 = W3[kk * H3 + lane + 32];
#pragma unroll
        for (int m = 0; m < TOK_PER_WARP; m++) {
            acc3[m][0] = fmaf(xk[m], w0, acc3[m][0]);
            acc3[m][1] = fmaf(xk[m], w1, acc3[m][1]);
        }
    }
#pragma unroll
    for (int m = 0; m < TOK_PER_WARP; m++) {
        int t = (tok0 + m) % TT;
        float a30 = a3[t * H3 + lane];
        float a31 = a3[t * H3 + lane + 32];
        float v0 = acc3[m][0], v1 = acc3[m][1];
        acc3[m][0] = (v0 > 0.f) ? v0 : a30 * v0;
        acc3[m][1] = (v1 > 0.f) ? v1 : a31 * v1;
    }

    // ---------------- Score: h3 @ Wl + bl, masked by k[...,0] != 0
    float wl0 = Wl[lane];
    float wl1 = Wl[lane + 32];
    float blv = bl[0];
    float score[TOK_PER_WARP];
#pragma unroll
    for (int m = 0; m < TOK_PER_WARP; m++) {
        float p = acc3[m][0] * wl0 + acc3[m][1] * wl1;
#pragma unroll
        for (int off = 16; off >= 1; off >>= 1)
            p += __shfl_xor_sync(0xFFFFFFFFu, p, off);
        float s = p + blv;
        float k00 = kv_sm[(m0 + m) * DD + 0];   // broadcast LDS
        score[m] = (k00 != 0.f) ? s : 0.f;
    }

    // ---------------- Pooling: out[b,:] += sum_m score[m]*k[m,:]
    // 8 consecutive tokens span at most 2 batches.
    int bF = tok0 / TT;
    int bL = (tok0 + TOK_PER_WARP - 1) / TT;
    float s0a = 0.f, s0b = 0.f, s1a = 0.f, s1b = 0.f;
#pragma unroll
    for (int m = 0; m < TOK_PER_WARP; m++) {
        int bm = (tok0 + m) / TT;
        float c0 = score[m] * kv_sm[(m0 + m) * DD + lane];
        float c1 = score[m] * kv_sm[(m0 + m) * DD + 32 + lane];
        if (bm == bF) { s0a += c0; s0b += c1; }
        else          { s1a += c0; s1b += c1; }
    }
    atomicAdd(&out[bF * DD + lane],      s0a);
    atomicAdd(&out[bF * DD + 32 + lane], s0b);
    if (bL != bF) {
        atomicAdd(&out[bL * DD + lane],      s1a);
        atomicAdd(&out[bL * DD + 32 + lane], s1b);
    }
}

// ---------------------------------------------------------------------------
extern "C" void kernel_launch(void* const* d_in, const int* in_sizes, int n_in,
                              void* d_out, int out_size) {
    const float* q  = (const float*)d_in[0];
    const float* k  = (const float*)d_in[1];
    const float* W1 = (const float*)d_in[2];
    const float* b1 = (const float*)d_in[3];
    const float* a1 = (const float*)d_in[4];
    const float* W2 = (const float*)d_in[5];
    const float* b2 = (const float*)d_in[6];
    const float* a2 = (const float*)d_in[7];
    const float* W3 = (const float*)d_in[8];
    const float* b3 = (const float*)d_in[9];
    const float* a3 = (const float*)d_in[10];
    const float* Wl = (const float*)d_in[11];
    const float* bl = (const float*)d_in[12];
    float* out = (float*)d_out;

    size_t smem_bytes = SMEM_FLOATS * sizeof(float);   // 64 KB
    cudaFuncSetAttribute(attn_pool_main,
                         cudaFuncAttributeMaxDynamicSharedMemorySize,
                         (int)smem_bytes);

    cudaMemsetAsync(d_out, 0, (size_t)BB * DD * sizeof(float));
    fold_w1_kernel<<<(DD * H1 + 255) / 256, 256>>>(W1);
    qproj_kernel<<<BB, H1>>>(q, W1, b1);
    attn_pool_main<<<NBLK, 128, smem_bytes>>>(q, k, W1, a1, W2, b2, a2,
                                              W3, b3, a3, Wl, bl, out);
}

// round 3
// speedup vs baseline: 2.0844x; 2.0844x over previous
#include <cuda_runtime.h>
#include <cuda_bf16.h>
#include <cstdint>

// ---------------- problem constants ----------------
#define BB 2048
#define TT 200
#define DD 64
#define H1 256
#define H2 128
#define H3 64
#define NTOK (BB * TT)          // 409600
#define MTILE 128               // tokens per CTA
#define NBLK (NTOK / MTILE)     // 3200
#define THREADS 256

// smem pitches (in floats / words). pitch%32==4 for fp32 v2 loads,
// pitch%32==8 for b32 B-fragment loads -> conflict-free patterns.
#define APITCH  260             // A2: K=256 fp32
#define A3PITCH 132             // A3: K=128 fp32 (overlays A2 region)
#define KPITCH  68              // k tile: 64 fp32
#define BPITCH  136             // B chunks with N=128
#define BPITCH3 72              // B chunks with N=64

// smem float offsets
#define OFF_A    0
#define OFF_K    (128 * APITCH)                 // 33280
#define OFF_BH   (OFF_K + 128 * KPITCH)         // 41984
#define OFF_BL   (OFF_BH + 32 * BPITCH)         // 46336
#define OFF_Q    (OFF_BL + 32 * BPITCH)         // 50688  q_sm[2][64]
#define OFF_QP   (OFF_Q + 128)                  // qproj_sm[2][256]
#define OFF_B2   (OFF_QP + 512)
#define OFF_B3   (OFF_B2 + 128)
#define OFF_WL   (OFF_B3 + 64)
#define OFF_PART (OFF_WL + 64)                  // part[128][2]
#define OFF_SC   (OFF_PART + 256)               // scores[128]
#define SMEM_FLOATS (OFF_SC + 128)
#define SMEM_BYTES (SMEM_FLOATS * 4)            // ~208 KB

// ---------------- device scratch (allocation-free rule) ----------------
__device__ float g_qproj[BB * H1];            // q@(W1a+W1c)+b1
// weight pairs: word[kp][n] = pack_bf16x2(B[2kp][n], B[2kp+1][n]); hi & lo split
__device__ uint32_t g_B1h[64 * H1],  g_B1l[64 * H1];    // layer1: K=128, N=256
__device__ uint32_t g_B2h[128 * H2], g_B2l[128 * H2];   // layer2: K=256, N=128
__device__ uint32_t g_B3h[64 * H3],  g_B3l[64 * H3];    // layer3: K=128, N=64

// ---------------- helpers ----------------
__device__ __forceinline__ void split2(float x, float y, uint32_t& hi, uint32_t& lo) {
    __nv_bfloat16 xh = __float2bfloat16(x);
    __nv_bfloat16 yh = __float2bfloat16(y);
    __nv_bfloat16 xl = __float2bfloat16(x - __bfloat162float(xh));
    __nv_bfloat16 yl = __float2bfloat16(y - __bfloat162float(yh));
    __nv_bfloat162 h(xh, yh), l(xl, yl);
    hi = *reinterpret_cast<uint32_t*>(&h);
    lo = *reinterpret_cast<uint32_t*>(&l);
}

__device__ __forceinline__ void mma16816(float c[4], const uint32_t a[4],
                                         uint32_t b0, uint32_t b1) {
    asm volatile(
        "mma.sync.aligned.m16n8k16.row.col.f32.bf16.bf16.f32 "
        "{%0,%1,%2,%3},{%4,%5,%6,%7},{%8,%9},{%0,%1,%2,%3};"
        : "+f"(c[0]), "+f"(c[1]), "+f"(c[2]), "+f"(c[3])
        : "r"(a[0]), "r"(a[1]), "r"(a[2]), "r"(a[3]), "r"(b0), "r"(b1));
}

// ---------------- prep kernels ----------------
__global__ void prep_weights(const float* __restrict__ W1,
                             const float* __restrict__ W2,
                             const float* __restrict__ W3) {
    int idx = blockIdx.x * blockDim.x + threadIdx.x;   // 0..16383
    {   // B1: kp 0..63, n 0..255.  k<64: W1b-W1c ; k>=64: W1d (row 128+k)
        int kp = idx >> 8, n = idx & 255;
        int k0 = 2 * kp, k1 = 2 * kp + 1;
        float v0 = (k0 < 64) ? (W1[(64 + k0) * H1 + n] - W1[(128 + k0) * H1 + n])
                             : W1[(128 + k0) * H1 + n];
        float v1 = (k1 < 64) ? (W1[(64 + k1) * H1 + n] - W1[(128 + k1) * H1 + n])
                             : W1[(128 + k1) * H1 + n];
        split2(v0, v1, g_B1h[idx], g_B1l[idx]);
    }
    {   // B2: kp 0..127, n 0..127
        int kp = idx >> 7, n = idx & 127;
        float v0 = W2[(2 * kp) * H2 + n];
        float v1 = W2[(2 * kp + 1) * H2 + n];
        split2(v0, v1, g_B2h[idx], g_B2l[idx]);
    }
    if (idx < 64 * H3) {   // B3: kp 0..63, n 0..63
        int kp = idx >> 6, n = idx & 63;
        float v0 = W3[(2 * kp) * H3 + n];
        float v1 = W3[(2 * kp + 1) * H3 + n];
        split2(v0, v1, g_B3h[idx], g_B3l[idx]);
    }
}

__global__ void qproj_kernel(const float* __restrict__ q,
                             const float* __restrict__ W1,
                             const float* __restrict__ b1) {
    __shared__ float qs[DD];
    int b = blockIdx.x;
    int n = threadIdx.x;
    if (n < DD) qs[n] = q[b * DD + n];
    __syncthreads();
    float acc = b1[n];
#pragma unroll 8
    for (int i = 0; i < DD; i++)
        acc = fmaf(qs[i], W1[i * H1 + n] + W1[(2 * DD + i) * H1 + n], acc);
    g_qproj[b * H1 + n] = acc;
}

// ---------------- main fused kernel ----------------
__global__ void __launch_bounds__(THREADS, 1)
attn_mma(const float* __restrict__ q,
         const float* __restrict__ kten,
         const float* __restrict__ a1,
         const float* __restrict__ a2,
         const float* __restrict__ a3,
         const float* __restrict__ Wl,
         const float* __restrict__ bl,
         const float* __restrict__ b2g,
         const float* __restrict__ b3g,
         float* __restrict__ out) {
    extern __shared__ float sm[];
    float*    A    = sm + OFF_A;
    float*    ksm  = sm + OFF_K;
    uint32_t* Bh   = (uint32_t*)(sm + OFF_BH);
    uint32_t* Bl   = (uint32_t*)(sm + OFF_BL);
    float*    qsm  = sm + OFF_Q;
    float*    qpsm = sm + OFF_QP;
    float*    b2s  = sm + OFF_B2;
    float*    b3s  = sm + OFF_B3;
    float*    wls  = sm + OFF_WL;
    float*    part = sm + OFF_PART;
    float*    scs  = sm + OFF_SC;

    const int tid  = threadIdx.x;
    const int w    = tid >> 5;
    const int lane = tid & 31;
    const int g    = lane >> 2;       // 0..7
    const int t    = lane & 3;        // 0..3
    const int T0   = blockIdx.x * MTILE;
    const int bA   = T0 / TT;
    const int bsplit = (bA + 1) * TT;
    const int bB   = (bA + 1 < BB) ? (bA + 1) : bA;
    const float blv = bl[0];

    // warp tile coords (layers 1 & 2: M32 x N64 within 128x128 span)
    const int mrow0 = (w & 3) * 32;
    const int ncol0 = (w >> 2) * 64;

    // ---- stage k (fp32, pitch 68), q, qproj, b2, b3, Wl
    {
        const float2* src = (const float2*)(kten + (size_t)T0 * DD);
        for (int i = tid; i < 128 * 32; i += THREADS) {
            int r = i >> 5, c2 = i & 31;
            float2 v = src[r * 32 + c2];
            ksm[r * KPITCH + 2 * c2]     = v.x;
            ksm[r * KPITCH + 2 * c2 + 1] = v.y;
        }
        if (tid < 128) {
            int bi = tid >> 6, c = tid & 63;
            qsm[tid] = q[(size_t)(bi ? bB : bA) * DD + c];
        }
        for (int i = tid; i < 512; i += THREADS) {
            int bi = i >> 8, c = i & 255;
            qpsm[i] = g_qproj[(size_t)(bi ? bB : bA) * H1 + c];
        }
        if (tid < 128) b2s[tid] = b2g[tid];
        if (tid < 64)  b3s[tid] = b3g[tid];
        if (tid >= 64 && tid < 128) wls[tid - 64] = Wl[tid - 64];
    }
    __syncthreads();

    // ================= Layer 1: [128,256] = A1[128,128] x B1, N in 2 halves
#pragma unroll 1
    for (int h = 0; h < 2; h++) {
        float acc[2][8][4];
#pragma unroll
        for (int ms = 0; ms < 2; ms++)
#pragma unroll
            for (int ns = 0; ns < 8; ns++)
#pragma unroll
                for (int e = 0; e < 4; e++) acc[ms][ns][e] = 0.f;

#pragma unroll 1
        for (int kc = 0; kc < 2; kc++) {
            __syncthreads();
            for (int i = tid; i < 32 * 128; i += THREADS) {
                int r = i >> 7, c = i & 127;
                int gsrc = (kc * 32 + r) * 256 + h * 128 + c;
                Bh[r * BPITCH + c] = g_B1h[gsrc];
                Bl[r * BPITCH + c] = g_B1l[gsrc];
            }
            __syncthreads();
#pragma unroll
            for (int si = 0; si < 4; si++) {
                int s = kc * 4 + si;
                uint32_t ah[2][4], al[2][4];
#pragma unroll
                for (int ms = 0; ms < 2; ms++) {
                    int rb = mrow0 + ms * 16 + g;
#pragma unroll
                    for (int fo = 0; fo < 4; fo++) {
                        int r  = rb + ((fo & 1) ? 8 : 0);
                        int co = 2 * t + ((fo >= 2) ? 8 : 0);
                        float x, y;
                        if (s < 4) {
                            float2 kv = *(const float2*)&ksm[r * KPITCH + s * 16 + co];
                            x = kv.x; y = kv.y;
                        } else {
                            int c = (s - 4) * 16 + co;
                            int bi = (T0 + r) >= bsplit;
                            float2 kv = *(const float2*)&ksm[r * KPITCH + c];
                            float2 qv = *(const float2*)&qsm[bi * 64 + c];
                            x = kv.x * qv.x; y = kv.y * qv.y;
                        }
                        split2(x, y, ah[ms][fo], al[ms][fo]);
                    }
                }
#pragma unroll
                for (int ns = 0; ns < 8; ns++) {
                    int bcol = ncol0 + ns * 8 + g;
                    uint32_t b0h = Bh[(si * 8 + t) * BPITCH + bcol];
                    uint32_t b1h = Bh[(si * 8 + t + 4) * BPITCH + bcol];
                    uint32_t b0l = Bl[(si * 8 + t) * BPITCH + bcol];
                    uint32_t b1l = Bl[(si * 8 + t + 4) * BPITCH + bcol];
#pragma unroll
                    for (int ms = 0; ms < 2; ms++) {
                        mma16816(acc[ms][ns], ah[ms], b0h, b1h);
                        mma16816(acc[ms][ns], ah[ms], b0l, b1l);
                        mma16816(acc[ms][ns], al[ms], b0h, b1h);
                    }
                }
            }
        }
        // epilogue half h -> A2 (fp32, pitch 260)
#pragma unroll
        for (int ms = 0; ms < 2; ms++)
#pragma unroll
            for (int ro = 0; ro < 2; ro++) {
                int r   = mrow0 + ms * 16 + ro * 8 + g;
                int tok = T0 + r;
                int bt  = tok >= bsplit;
                int tt  = tok - (bt ? bsplit : bA * TT);
#pragma unroll
                for (int ns = 0; ns < 8; ns++) {
                    int col = h * 128 + ncol0 + ns * 8 + 2 * t;
                    float v0 = acc[ms][ns][ro * 2]     + qpsm[bt * 256 + col];
                    float v1 = acc[ms][ns][ro * 2 + 1] + qpsm[bt * 256 + col + 1];
                    float2 av = *(const float2*)&a1[(size_t)tt * H1 + col];
                    v0 = v0 > 0.f ? v0 : v0 * av.x;
                    v1 = v1 > 0.f ? v1 : v1 * av.y;
                    A[r * APITCH + col]     = v0;
                    A[r * APITCH + col + 1] = v1;
                }
            }
    }
    __syncthreads();

    // ================= Layer 2: [128,128] = A2[128,256] x B2
    {
        float acc[2][8][4];
#pragma unroll
        for (int ms = 0; ms < 2; ms++)
#pragma unroll
            for (int ns = 0; ns < 8; ns++)
#pragma unroll
                for (int e = 0; e < 4; e++) acc[ms][ns][e] = 0.f;

#pragma unroll 1
        for (int kc = 0; kc < 4; kc++) {
            __syncthreads();
            for (int i = tid; i < 32 * 128; i += THREADS) {
                int r = i >> 7, c = i & 127;
                int gsrc = (kc * 32 + r) * 128 + c;
                Bh[r * BPITCH + c] = g_B2h[gsrc];
                Bl[r * BPITCH + c] = g_B2l[gsrc];
            }
            __syncthreads();
#pragma unroll
            for (int si = 0; si < 4; si++) {
                int s = kc * 4 + si;
                uint32_t ah[2][4], al[2][4];
#pragma unroll
                for (int ms = 0; ms < 2; ms++) {
                    int rb = mrow0 + ms * 16 + g;
#pragma unroll
                    for (int fo = 0; fo < 4; fo++) {
                        int r  = rb + ((fo & 1) ? 8 : 0);
                        int co = 2 * t + ((fo >= 2) ? 8 : 0);
                        float2 v = *(const float2*)&A[r * APITCH + s * 16 + co];
                        split2(v.x, v.y, ah[ms][fo], al[ms][fo]);
                    }
                }
#pragma unroll
                for (int ns = 0; ns < 8; ns++) {
                    int bcol = ncol0 + ns * 8 + g;
                    uint32_t b0h = Bh[(si * 8 + t) * BPITCH + bcol];
                    uint32_t b1h = Bh[(si * 8 + t + 4) * BPITCH + bcol];
                    uint32_t b0l = Bl[(si * 8 + t) * BPITCH + bcol];
                    uint32_t b1l = Bl[(si * 8 + t + 4) * BPITCH + bcol];
#pragma unroll
                    for (int ms = 0; ms < 2; ms++) {
                        mma16816(acc[ms][ns], ah[ms], b0h, b1h);
                        mma16816(acc[ms][ns], ah[ms], b0l, b1l);
                        mma16816(acc[ms][ns], al[ms], b0h, b1h);
                    }
                }
            }
        }
        __syncthreads();   // all warps done reading A2 before A3 overwrite
        // epilogue -> A3 (fp32, pitch 132)
#pragma unroll
        for (int ms = 0; ms < 2; ms++)
#pragma unroll
            for (int ro = 0; ro < 2; ro++) {
                int r   = mrow0 + ms * 16 + ro * 8 + g;
                int tok = T0 + r;
                int bt  = tok >= bsplit;
                int tt  = tok - (bt ? bsplit : bA * TT);
#pragma unroll
                for (int ns = 0; ns < 8; ns++) {
                    int col = ncol0 + ns * 8 + 2 * t;
                    float v0 = acc[ms][ns][ro * 2]     + b2s[col];
                    float v1 = acc[ms][ns][ro * 2 + 1] + b2s[col + 1];
                    float2 av = *(const float2*)&a2[(size_t)tt * H2 + col];
                    v0 = v0 > 0.f ? v0 : v0 * av.x;
                    v1 = v1 > 0.f ? v1 : v1 * av.y;
                    A[r * A3PITCH + col]     = v0;
                    A[r * A3PITCH + col + 1] = v1;
                }
            }
    }

    // ================= Layer 3: [128,64] = A3[128,128] x B3 ; scores
    {
        const int ncol3 = (w >> 2) * 32;   // M32 x N32 warp tiles
        float acc[2][4][4];
#pragma unroll
        for (int ms = 0; ms < 2; ms++)
#pragma unroll
            for (int ns = 0; ns < 4; ns++)
#pragma unroll
                for (int e = 0; e < 4; e++) acc[ms][ns][e] = 0.f;

#pragma unroll 1
        for (int kc = 0; kc < 2; kc++) {
            __syncthreads();
            for (int i = tid; i < 32 * 64; i += THREADS) {
                int r = i >> 6, c = i & 63;
                int gsrc = (kc * 32 + r) * 64 + c;
                Bh[r * BPITCH3 + c] = g_B3h[gsrc];
                Bl[r * BPITCH3 + c] = g_B3l[gsrc];
            }
            __syncthreads();
#pragma unroll
            for (int si = 0; si < 4; si++) {
                int s = kc * 4 + si;
                uint32_t ah[2][4], al[2][4];
#pragma unroll
                for (int ms = 0; ms < 2; ms++) {
                    int rb = mrow0 + ms * 16 + g;
#pragma unroll
                    for (int fo = 0; fo < 4; fo++) {
                        int r  = rb + ((fo & 1) ? 8 : 0);
                        int co = 2 * t + ((fo >= 2) ? 8 : 0);
                        float2 v = *(const float2*)&A[r * A3PITCH + s * 16 + co];
                        split2(v.x, v.y, ah[ms][fo], al[ms][fo]);
                    }
                }
#pragma unroll
                for (int ns = 0; ns < 4; ns++) {
                    int bcol = ncol3 + ns * 8 + g;
                    uint32_t b0h = Bh[(si * 8 + t) * BPITCH3 + bcol];
                    uint32_t b1h = Bh[(si * 8 + t + 4) * BPITCH3 + bcol];
                    uint32_t b0l = Bl[(si * 8 + t) * BPITCH3 + bcol];
                    uint32_t b1l = Bl[(si * 8 + t + 4) * BPITCH3 + bcol];
#pragma unroll
                    for (int ms = 0; ms < 2; ms++) {
                        mma16816(acc[ms][ns], ah[ms], b0h, b1h);
                        mma16816(acc[ms][ns], ah[ms], b0l, b1l);
                        mma16816(acc[ms][ns], al[ms], b0h, b1h);
                    }
                }
            }
        }
        // epilogue: PReLU + dot with Wl -> per-row partials
#pragma unroll
        for (int ms = 0; ms < 2; ms++)
#pragma unroll
            for (int ro = 0; ro < 2; ro++) {
                int r   = mrow0 + ms * 16 + ro * 8 + g;
                int tok = T0 + r;
                int bt  = tok >= bsplit;
                int tt  = tok - (bt ? bsplit : bA * TT);
                float rp = 0.f;
#pragma unroll
                for (int ns = 0; ns < 4; ns++) {
                    int col = ncol3 + ns * 8 + 2 * t;
                    float v0 = acc[ms][ns][ro * 2]     + b3s[col];
                    float v1 = acc[ms][ns][ro * 2 + 1] + b3s[col + 1];
                    float2 av = *(const float2*)&a3[(size_t)tt * H3 + col];
                    v0 = v0 > 0.f ? v0 : v0 * av.x;
                    v1 = v1 > 0.f ? v1 : v1 * av.y;
                    rp = fmaf(v0, wls[col], rp);
                    rp = fmaf(v1, wls[col + 1], rp);
                }
                rp += __shfl_xor_sync(0xFFFFFFFFu, rp, 1);
                rp += __shfl_xor_sync(0xFFFFFFFFu, rp, 2);
                if (t == 0) part[r * 2 + (w >> 2)] = rp;
            }
    }
    __syncthreads();

    // finalize scores + mask
    if (tid < 128) {
        float sc = part[tid * 2] + part[tid * 2 + 1] + blv;
        scs[tid] = (ksm[tid * KPITCH] != 0.f) ? sc : 0.f;
    }
    __syncthreads();

    // ---- pooling: warp w handles tokens [w*16, w*16+16)
    {
        int r0 = w * 16;
        int bF = (T0 + r0) / TT;
        int bL = (T0 + r0 + 15) / TT;
        float s0a = 0.f, s0b = 0.f, s1a = 0.f, s1b = 0.f;
#pragma unroll
        for (int j = 0; j < 16; j++) {
            int r = r0 + j;
            float s  = scs[r];
            float c0 = s * ksm[r * KPITCH + lane];
            float c1 = s * ksm[r * KPITCH + 32 + lane];
            if ((T0 + r) / TT == bF) { s0a += c0; s0b += c1; }
            else                     { s1a += c0; s1b += c1; }
        }
        atomicAdd(&out[bF * DD + lane],      s0a);
        atomicAdd(&out[bF * DD + 32 + lane], s0b);
        if (bL != bF) {
            atomicAdd(&out[bL * DD + lane],      s1a);
            atomicAdd(&out[bL * DD + 32 + lane], s1b);
        }
    }
}

// ---------------------------------------------------------------------------
extern "C" void kernel_launch(void* const* d_in, const int* in_sizes, int n_in,
                              void* d_out, int out_size) {
    const float* q  = (const float*)d_in[0];
    const float* k  = (const float*)d_in[1];
    const float* W1 = (const float*)d_in[2];
    const float* b1 = (const float*)d_in[3];
    const float* a1 = (const float*)d_in[4];
    const float* W2 = (const float*)d_in[5];
    const float* b2 = (const float*)d_in[6];
    const float* a2 = (const float*)d_in[7];
    const float* W3 = (const float*)d_in[8];
    const float* b3 = (const float*)d_in[9];
    const float* a3 = (const float*)d_in[10];
    const float* Wl = (const float*)d_in[11];
    const float* bl = (const float*)d_in[12];
    float* out = (float*)d_out;

    cudaFuncSetAttribute(attn_mma,
                         cudaFuncAttributeMaxDynamicSharedMemorySize, SMEM_BYTES);

    cudaMemsetAsync(d_out, 0, (size_t)BB * DD * sizeof(float));
    prep_weights<<<64, 256>>>(W1, W2, W3);
    qproj_kernel<<<BB, H1>>>(q, W1, b1);
    attn_mma<<<NBLK, THREADS, SMEM_BYTES>>>(q, k, a1, a2, a3, Wl, bl, b2, b3, out);
}

// round 4
// speedup vs baseline: 2.8392x; 1.3621x over previous
#include <cuda_runtime.h>
#include <cuda_bf16.h>
#include <cstdint>

// ---------------- problem constants ----------------
#define BB 2048
#define TT 200
#define DD 64
#define H1 256
#define H2 128
#define H3 64
#define NTOK (BB * TT)
#define MTILE 128
#define NBLK (NTOK / MTILE)     // 3200
#define THREADS 256

// ---------------- smem layout (uint32 word offsets) ----------------
#define APITCH 68               // words per A-plane row (64 data + 4 pad)
#define BPITCH 20               // words per B-stage row (16 data + 4 pad)
#define BSTAGE_WORDS (128 * BPITCH)     // 2560
#define BSTAGE_PAIR  (2 * BSTAGE_WORDS) // hi+lo = 5120

#define OFF_A1H 0
#define OFF_A1L (OFF_A1H + 128 * APITCH)      // 8704
#define OFF_A2H (OFF_A1L + 128 * APITCH)      // 17408
#define OFF_A2L (OFF_A2H + 128 * APITCH)      // 26112
#define OFF_BST (OFF_A2L + 128 * APITCH)      // 34816, 3 stages
#define OFF_QP  (OFF_BST + 3 * BSTAGE_PAIR)   // 50176
#define OFF_K0  (OFF_QP + 512)
#define OFF_B2S (OFF_K0 + 128)
#define OFF_B3S (OFF_B2S + 128)
#define OFF_WL  (OFF_B3S + 64)
#define OFF_PART (OFF_WL + 64)
#define OFF_SC  (OFF_PART + 256)
#define SMEM_WORDS (OFF_SC + 128)             // 51456
#define SMEM_BYTES (SMEM_WORDS * 4)           // 205824

#define NCHUNK 20

// ---------------- device scratch ----------------
__device__ float g_qproj[BB * H1];
// packed, pre-split, consumption-ordered B chunks:
// [chunk 20][plane 2 (hi,lo)][n 128][kpair 16] uint32 = bf16x2(k even, k odd)
__device__ __align__(16) uint32_t g_Ball[NCHUNK * 4096];

// ---------------- helpers ----------------
__device__ __forceinline__ uint32_t smem_u32(const void* p) {
    uint32_t a;
    asm("{ .reg .u64 t; cvta.to.shared.u64 t, %1; cvt.u32.u64 %0, t; }"
        : "=r"(a) : "l"(p));
    return a;
}

__device__ __forceinline__ void split2(float x, float y, uint32_t& hi, uint32_t& lo) {
    __nv_bfloat16 xh = __float2bfloat16(x);
    __nv_bfloat16 yh = __float2bfloat16(y);
    __nv_bfloat16 xl = __float2bfloat16(x - __bfloat162float(xh));
    __nv_bfloat16 yl = __float2bfloat16(y - __bfloat162float(yh));
    __nv_bfloat162 h(xh, yh), l(xl, yl);
    hi = *reinterpret_cast<uint32_t*>(&h);
    lo = *reinterpret_cast<uint32_t*>(&l);
}

__device__ __forceinline__ void mma16816(float c[4], const uint32_t a[4],
                                         uint32_t b0, uint32_t b1) {
    asm volatile(
        "mma.sync.aligned.m16n8k16.row.col.f32.bf16.bf16.f32 "
        "{%0,%1,%2,%3},{%4,%5,%6,%7},{%8,%9},{%0,%1,%2,%3};"
        : "+f"(c[0]), "+f"(c[1]), "+f"(c[2]), "+f"(c[3])
        : "r"(a[0]), "r"(a[1]), "r"(a[2]), "r"(a[3]), "r"(b0), "r"(b1));
}

__device__ __forceinline__ void ldmat4(uint32_t r[4], uint32_t addr) {
    asm volatile("ldmatrix.sync.aligned.m8n8.x4.shared.b16 {%0,%1,%2,%3}, [%4];"
                 : "=r"(r[0]), "=r"(r[1]), "=r"(r[2]), "=r"(r[3]) : "r"(addr));
}

#define CP_ASYNC16(dst, src) \
    asm volatile("cp.async.cg.shared.global [%0], [%1], 16;" :: "r"(dst), "l"(src))
#define CP_COMMIT() asm volatile("cp.async.commit_group;" ::: "memory")
#define CP_WAIT1()  asm volatile("cp.async.wait_group 1;" ::: "memory")
#define CP_WAIT0()  asm volatile("cp.async.wait_group 0;" ::: "memory")

// issue async copy of chunk nc into stage buffer (nc % 3)
__device__ __forceinline__ void stage_issue(int nc, uint32_t smbase, int tid) {
    uint32_t dstbase = OFF_BST + (nc % 3) * BSTAGE_PAIR;
    const uint32_t* gsrc = g_Ball + nc * 4096;
#pragma unroll
    for (int j = 0; j < 4; j++) {
        int u = tid + j * 256;
        int plane = u >> 9, rem = u & 511, n = rem >> 2, seg = rem & 3;
        uint32_t dst = smbase + (dstbase + plane * BSTAGE_WORDS + n * BPITCH + seg * 4) * 4;
        CP_ASYNC16(dst, gsrc + plane * 2048 + n * 16 + seg * 4);
    }
}

// top-of-chunk: wait for chunk seq, barrier, prefetch chunk seq+2
__device__ __forceinline__ void chunk_pre(int seq, uint32_t smbase, int tid) {
    if (seq >= NCHUNK - 2) CP_WAIT0(); else CP_WAIT1();
    __syncthreads();
    if (seq + 2 < NCHUNK) {
        stage_issue(seq + 2, smbase, tid);
        CP_COMMIT();
    }
}

// one B-chunk (2 k16-steps) of 3-product MMAs. NP = #ldmatrix n-pairs (4 or 2).
// acc is [2][2*NP][4] flattened to [2*2*NP][4].
template <int NP>
__device__ __forceinline__ void chunk_mma(float (*acc)[4],
                                          uint32_t aH0, uint32_t aH1,
                                          uint32_t aL0, uint32_t aL1,
                                          uint32_t bH, uint32_t bL) {
    const int NS = 2 * NP;
#pragma unroll
    for (int sl = 0; sl < 2; sl++) {
        uint32_t A0h[4], A1h[4], A0l[4], A1l[4];
        ldmat4(A0h, aH0 + sl * 32);
        ldmat4(A1h, aH1 + sl * 32);
        ldmat4(A0l, aL0 + sl * 32);
        ldmat4(A1l, aL1 + sl * 32);
#pragma unroll
        for (int p = 0; p < NP; p++) {
            uint32_t bh[4], bl_[4];
            ldmat4(bh,  bH + p * 1280 + sl * 32);
            ldmat4(bl_, bL + p * 1280 + sl * 32);
            mma16816(acc[0 * NS + 2 * p],     A0h, bh[0],  bh[1]);
            mma16816(acc[0 * NS + 2 * p],     A0h, bl_[0], bl_[1]);
            mma16816(acc[0 * NS + 2 * p],     A0l, bh[0],  bh[1]);
            mma16816(acc[0 * NS + 2 * p + 1], A0h, bh[2],  bh[3]);
            mma16816(acc[0 * NS + 2 * p + 1], A0h, bl_[2], bl_[3]);
            mma16816(acc[0 * NS + 2 * p + 1], A0l, bh[2],  bh[3]);
            mma16816(acc[1 * NS + 2 * p],     A1h, bh[0],  bh[1]);
            mma16816(acc[1 * NS + 2 * p],     A1h, bl_[0], bl_[1]);
            mma16816(acc[1 * NS + 2 * p],     A1l, bh[0],  bh[1]);
            mma16816(acc[1 * NS + 2 * p + 1], A1h, bh[2],  bh[3]);
            mma16816(acc[1 * NS + 2 * p + 1], A1h, bl_[2], bl_[3]);
            mma16816(acc[1 * NS + 2 * p + 1], A1l, bh[2],  bh[3]);
        }
    }
}

// ---------------- merged prep kernel (weights + qproj + out zero) ----------
__global__ void prep_all(const float* __restrict__ W1,
                         const float* __restrict__ W2,
                         const float* __restrict__ W3,
                         const float* __restrict__ q,
                         const float* __restrict__ b1,
                         float* __restrict__ out) {
    int blk = blockIdx.x, tid = threadIdx.x;
    if (blk < 160) {
        int e = blk * 256 + tid;                 // 0..40959
        int c = e >> 11, rem = e & 2047, n = rem >> 4, kpl = rem & 15;
        float v0, v1;
        if (c < 4 || (c >= 8 && c < 12)) {       // B1 (chunks 0-3 half0, 8-11 half1)
            int half = (c >= 8);
            int kp = (c & 3) * 16 + kpl;
            int ng = half * 128 + n;
            int k0i = 2 * kp, k1i = k0i + 1;
            v0 = (k0i < 64) ? (W1[(64 + k0i) * H1 + ng] - W1[(128 + k0i) * H1 + ng])
                            : W1[(128 + k0i) * H1 + ng];
            v1 = (k1i < 64) ? (W1[(64 + k1i) * H1 + ng] - W1[(128 + k1i) * H1 + ng])
                            : W1[(128 + k1i) * H1 + ng];
        } else if (c < 8) {                      // B2 kp 0..63
            int kp = (c - 4) * 16 + kpl;
            v0 = W2[(2 * kp) * H2 + n];
            v1 = W2[(2 * kp + 1) * H2 + n];
        } else if (c < 16) {                     // B2 kp 64..127
            int kp = 64 + (c - 12) * 16 + kpl;
            v0 = W2[(2 * kp) * H2 + n];
            v1 = W2[(2 * kp + 1) * H2 + n];
        } else {                                 // B3 kp 0..63 (n padded to 128)
            int kp = (c - 16) * 16 + kpl;
            v0 = (n < 64) ? W3[(2 * kp) * H3 + n] : 0.f;
            v1 = (n < 64) ? W3[(2 * kp + 1) * H3 + n] : 0.f;
        }
        uint32_t hi, lo;
        split2(v0, v1, hi, lo);
        g_Ball[c * 4096 + n * 16 + kpl]        = hi;
        g_Ball[c * 4096 + 2048 + n * 16 + kpl] = lo;
    } else {
        int b = blk - 160;
        __shared__ float qs[DD];
        int n = tid;
        if (n < DD) qs[n] = q[b * DD + n];
        __syncthreads();
        float acc = b1[n];
#pragma unroll 8
        for (int i = 0; i < DD; i++)
            acc = fmaf(qs[i], W1[i * H1 + n] + W1[(2 * DD + i) * H1 + n], acc);
        g_qproj[b * H1 + n] = acc;
        if (n < 64) out[b * 64 + n] = 0.f;       // replaces cudaMemsetAsync
    }
}

// ---------------- main fused kernel ----------------
__global__ void __launch_bounds__(THREADS, 1)
attn_mma2(const float* __restrict__ q,
          const float* __restrict__ kten,
          const float* __restrict__ a1,
          const float* __restrict__ a2,
          const float* __restrict__ a3,
          const float* __restrict__ Wl,
          const float* __restrict__ bl,
          const float* __restrict__ b2g,
          const float* __restrict__ b3g,
          float* __restrict__ out) {
    extern __shared__ uint32_t smw[];
    float* smf = (float*)smw;
    const uint32_t smbase = smem_u32(smw);

    const int tid  = threadIdx.x;
    const int w    = tid >> 5;
    const int lane = tid & 31;
    const int g    = lane >> 2;
    const int t    = lane & 3;
    const int T0   = blockIdx.x * MTILE;
    const int bA   = T0 / TT;
    const int bsplit = (bA + 1) * TT;
    const int bB   = (bA + 1 < BB) ? (bA + 1) : bA;
    const float blv = bl[0];

    const int mrow0 = (w & 3) * 32;
    const int ncol0 = (w >> 2) * 64;
    const int ncol3 = (w >> 2) * 32;

    // prologue: start chunks 0,1
    stage_issue(0, smbase, tid); CP_COMMIT();
    stage_issue(1, smbase, tid); CP_COMMIT();

    // ---- stage A1 planes (k: word cols 0..31, qk: 32..63), k0, qp, biases
    {
        int r = tid >> 1, hf = tid & 1;
        const float4* ksrc = (const float4*)(kten + (size_t)(T0 + r) * DD + hf * 32);
        int brow = (T0 + r) / TT;
        const float4* qsrc = (const float4*)(q + (size_t)brow * DD + hf * 32);
        uint32_t* a1h = smw + OFF_A1H + r * APITCH;
        uint32_t* a1l = smw + OFF_A1L + r * APITCH;
        uint32_t hi, lo;
#pragma unroll
        for (int i = 0; i < 8; i++) {
            float4 kk = ksrc[i];
            float4 qq = qsrc[i];
            int wc = hf * 16 + 2 * i;
            split2(kk.x, kk.y, hi, lo);
            a1h[wc] = hi; a1l[wc] = lo;
            split2(kk.z, kk.w, hi, lo);
            a1h[wc + 1] = hi; a1l[wc + 1] = lo;
            split2(kk.x * qq.x, kk.y * qq.y, hi, lo);
            a1h[32 + wc] = hi; a1l[32 + wc] = lo;
            split2(kk.z * qq.z, kk.w * qq.w, hi, lo);
            a1h[32 + wc + 1] = hi; a1l[32 + wc + 1] = lo;
            if (i == 0 && hf == 0) smf[OFF_K0 + r] = kk.x;
        }
        for (int i = tid; i < 512; i += THREADS) {
            int bi = i >> 8, c = i & 255;
            smf[OFF_QP + i] = g_qproj[(size_t)(bi ? bB : bA) * H1 + c];
        }
        if (tid < 128) smf[OFF_B2S + tid] = b2g[tid];
        if (tid < 64)  smf[OFF_B3S + tid] = b3g[tid];
        if (tid >= 64 && tid < 128) smf[OFF_WL + tid - 64] = Wl[tid - 64];
    }

    // ---- precompute ldmatrix lane addresses
    const uint32_t a_lane = (((lane & 15) * APITCH) + ((lane >> 4) << 2)) * 4;
    const uint32_t aH1_0 = smbase + (OFF_A1H + mrow0 * APITCH) * 4 + a_lane;
    const uint32_t aH1_1 = aH1_0 + 16 * APITCH * 4;
    const uint32_t aL1_0 = aH1_0 + (OFF_A1L - OFF_A1H) * 4;
    const uint32_t aL1_1 = aH1_1 + (OFF_A1L - OFF_A1H) * 4;
    const uint32_t aH2_0 = smbase + (OFF_A2H + mrow0 * APITCH) * 4 + a_lane;
    const uint32_t aH2_1 = aH2_0 + 16 * APITCH * 4;
    const uint32_t aL2_0 = aH2_0 + (OFF_A2L - OFF_A2H) * 4;
    const uint32_t aL2_1 = aH2_1 + (OFF_A2L - OFF_A2H) * 4;
    const uint32_t b_lane =
        ((((lane & 7) + ((lane >> 4) << 3)) * BPITCH) + (((lane >> 3) & 1) << 2)) * 4;
    const uint32_t bwarp12 = ncol0 * BPITCH * 4 + b_lane;
    const uint32_t bwarp3  = ncol3 * BPITCH * 4 + b_lane;

    float acc2[16][4];
#pragma unroll
    for (int i = 0; i < 16; i++)
#pragma unroll
        for (int e = 0; e < 4; e++) acc2[i][e] = 0.f;

    int seq = 0;
#pragma unroll 1
    for (int h = 0; h < 2; h++) {
        // ===== layer 1 (half h): D1 cols [h*128, h*128+128)
        float acc1[16][4];
#pragma unroll
        for (int i = 0; i < 16; i++)
#pragma unroll
            for (int e = 0; e < 4; e++) acc1[i][e] = 0.f;

#pragma unroll 1
        for (int kc = 0; kc < 4; kc++) {
            chunk_pre(seq, smbase, tid);
            uint32_t bufb = smbase + (OFF_BST + (seq % 3) * BSTAGE_PAIR) * 4;
            uint32_t bH = bufb + bwarp12;
            uint32_t bL = bH + BSTAGE_WORDS * 4;
            uint32_t wb = kc * 64;
            chunk_mma<4>(acc1, aH1_0 + wb, aH1_1 + wb, aL1_0 + wb, aL1_1 + wb, bH, bL);
            seq++;
        }

        // epilogue 1 -> A2 chunk planes (local word cols 0..63)
#pragma unroll
        for (int ms = 0; ms < 2; ms++)
#pragma unroll
            for (int ro = 0; ro < 2; ro++) {
                int r = mrow0 + ms * 16 + ro * 8 + g;
                int tok = T0 + r;
                int bt = tok >= bsplit;
                int tt = tok - (bt ? bsplit : bA * TT);
                const float* a1row = a1 + (size_t)tt * H1;
#pragma unroll
                for (int ns = 0; ns < 8; ns++) {
                    int gcol = h * 128 + ncol0 + ns * 8 + 2 * t;
                    float v0 = acc1[ms * 8 + ns][ro * 2]     + smf[OFF_QP + bt * 256 + gcol];
                    float v1 = acc1[ms * 8 + ns][ro * 2 + 1] + smf[OFF_QP + bt * 256 + gcol + 1];
                    float2 av = *(const float2*)&a1row[gcol];
                    v0 = v0 > 0.f ? v0 : v0 * av.x;
                    v1 = v1 > 0.f ? v1 : v1 * av.y;
                    uint32_t hi, lo;
                    split2(v0, v1, hi, lo);
                    int wc = (ncol0 >> 1) + ns * 4 + t;
                    smw[OFF_A2H + r * APITCH + wc] = hi;
                    smw[OFF_A2L + r * APITCH + wc] = lo;
                }
            }

        // ===== layer 2 partial: K cols [h*128, h*128+128) accumulate
#pragma unroll 1
        for (int kc = 0; kc < 4; kc++) {
            chunk_pre(seq, smbase, tid);   // barrier also publishes A2 writes
            uint32_t bufb = smbase + (OFF_BST + (seq % 3) * BSTAGE_PAIR) * 4;
            uint32_t bH = bufb + bwarp12;
            uint32_t bL = bH + BSTAGE_WORDS * 4;
            uint32_t wb = kc * 64;
            chunk_mma<4>(acc2, aH2_0 + wb, aH2_1 + wb, aL2_0 + wb, aL2_1 + wb, bH, bL);
            seq++;
        }
    }

    // ===== layer 2 epilogue -> A3 planes (reuse A2 buffers)
    __syncthreads();   // all warps done reading A2 before overwrite
#pragma unroll
    for (int ms = 0; ms < 2; ms++)
#pragma unroll
        for (int ro = 0; ro < 2; ro++) {
            int r = mrow0 + ms * 16 + ro * 8 + g;
            int tok = T0 + r;
            int bt = tok >= bsplit;
            int tt = tok - (bt ? bsplit : bA * TT);
            const float* a2row = a2 + (size_t)tt * H2;
#pragma unroll
            for (int ns = 0; ns < 8; ns++) {
                int col = ncol0 + ns * 8 + 2 * t;
                float v0 = acc2[ms * 8 + ns][ro * 2]     + smf[OFF_B2S + col];
                float v1 = acc2[ms * 8 + ns][ro * 2 + 1] + smf[OFF_B2S + col + 1];
                float2 av = *(const float2*)&a2row[col];
                v0 = v0 > 0.f ? v0 : v0 * av.x;
                v1 = v1 > 0.f ? v1 : v1 * av.y;
                uint32_t hi, lo;
                split2(v0, v1, hi, lo);
                int wc = (ncol0 >> 1) + ns * 4 + t;
                smw[OFF_A2H + r * APITCH + wc] = hi;
                smw[OFF_A2L + r * APITCH + wc] = lo;
            }
        }

    // ===== layer 3
    float acc3[8][4];
#pragma unroll
    for (int i = 0; i < 8; i++)
#pragma unroll
        for (int e = 0; e < 4; e++) acc3[i][e] = 0.f;

#pragma unroll 1
    for (int kc = 0; kc < 4; kc++) {
        chunk_pre(seq, smbase, tid);
        uint32_t bufb = smbase + (OFF_BST + (seq % 3) * BSTAGE_PAIR) * 4;
        uint32_t bH = bufb + bwarp3;
        uint32_t bL = bH + BSTAGE_WORDS * 4;
        uint32_t wb = kc * 64;
        chunk_mma<2>(acc3, aH2_0 + wb, aH2_1 + wb, aL2_0 + wb, aL2_1 + wb, bH, bL);
        seq++;
    }

    // epilogue 3: PReLU + dot(Wl) -> per-row partials
#pragma unroll
    for (int ms = 0; ms < 2; ms++)
#pragma unroll
        for (int ro = 0; ro < 2; ro++) {
            int r = mrow0 + ms * 16 + ro * 8 + g;
            int tok = T0 + r;
            int bt = tok >= bsplit;
            int tt = tok - (bt ? bsplit : bA * TT);
            const float* a3row = a3 + (size_t)tt * H3;
            float rp = 0.f;
#pragma unroll
            for (int ns = 0; ns < 4; ns++) {
                int col = ncol3 + ns * 8 + 2 * t;
                float v0 = acc3[ms * 4 + ns][ro * 2]     + smf[OFF_B3S + col];
                float v1 = acc3[ms * 4 + ns][ro * 2 + 1] + smf[OFF_B3S + col + 1];
                float2 av = *(const float2*)&a3row[col];
                v0 = v0 > 0.f ? v0 : v0 * av.x;
                v1 = v1 > 0.f ? v1 : v1 * av.y;
                rp = fmaf(v0, smf[OFF_WL + col], rp);
                rp = fmaf(v1, smf[OFF_WL + col + 1], rp);
            }
            rp += __shfl_xor_sync(0xFFFFFFFFu, rp, 1);
            rp += __shfl_xor_sync(0xFFFFFFFFu, rp, 2);
            if (t == 0) smf[OFF_PART + r * 2 + (w >> 2)] = rp;
        }
    __syncthreads();

    if (tid < 128) {
        float sc = smf[OFF_PART + tid * 2] + smf[OFF_PART + tid * 2 + 1] + blv;
        smf[OFF_SC + tid] = (smf[OFF_K0 + tid] != 0.f) ? sc : 0.f;
    }
    __syncthreads();

    // ---- pooling: warp w handles rows [w*16, w*16+16); k from A1 planes
    {
        int r0 = w * 16;
        int bF = (T0 + r0) / TT;
        int bL2 = (T0 + r0 + 15) / TT;
        float s0a = 0.f, s0b = 0.f, s1a = 0.f, s1b = 0.f;
#pragma unroll 4
        for (int j = 0; j < 16; j++) {
            int r = r0 + j;
            float s = smf[OFF_SC + r];
            uint32_t wh0 = smw[OFF_A1H + r * APITCH + (lane >> 1)];
            uint32_t wl0 = smw[OFF_A1L + r * APITCH + (lane >> 1)];
            uint32_t wh1 = smw[OFF_A1H + r * APITCH + 16 + (lane >> 1)];
            uint32_t wl1 = smw[OFF_A1L + r * APITCH + 16 + (lane >> 1)];
            __nv_bfloat162 h0 = *reinterpret_cast<__nv_bfloat162*>(&wh0);
            __nv_bfloat162 l0 = *reinterpret_cast<__nv_bfloat162*>(&wl0);
            __nv_bfloat162 h1 = *reinterpret_cast<__nv_bfloat162*>(&wh1);
            __nv_bfloat162 l1 = *reinterpret_cast<__nv_bfloat162*>(&wl1);
            float kv0 = (lane & 1) ? (__bfloat162float(h0.y) + __bfloat162float(l0.y))
                                   : (__bfloat162float(h0.x) + __bfloat162float(l0.x));
            float kv1 = (lane & 1) ? (__bfloat162float(h1.y) + __bfloat162float(l1.y))
                                   : (__bfloat162float(h1.x) + __bfloat162float(l1.x));
            if ((T0 + r) / TT == bF) { s0a = fmaf(s, kv0, s0a); s0b = fmaf(s, kv1, s0b); }
            else                     { s1a = fmaf(s, kv0, s1a); s1b = fmaf(s, kv1, s1b); }
        }
        atomicAdd(&out[bF * DD + lane],      s0a);
        atomicAdd(&out[bF * DD + 32 + lane], s0b);
        if (bL2 != bF) {
            atomicAdd(&out[bL2 * DD + lane],      s1a);
            atomicAdd(&out[bL2 * DD + 32 + lane], s1b);
        }
    }
}

// ---------------------------------------------------------------------------
extern "C" void kernel_launch(void* const* d_in, const int* in_sizes, int n_in,
                              void* d_out, int out_size) {
    const float* q  = (const float*)d_in[0];
    const float* k  = (const float*)d_in[1];
    const float* W1 = (const float*)d_in[2];
    const float* b1 = (const float*)d_in[3];
    const float* a1 = (const float*)d_in[4];
    const float* W2 = (const float*)d_in[5];
    const float* b2 = (const float*)d_in[6];
    const float* a2 = (const float*)d_in[7];
    const float* W3 = (const float*)d_in[8];
    const float* b3 = (const float*)d_in[9];
    const float* a3 = (const float*)d_in[10];
    const float* Wl = (const float*)d_in[11];
    const float* bl = (const float*)d_in[12];
    float* out = (float*)d_out;

    cudaFuncSetAttribute(attn_mma2,
                         cudaFuncAttributeMaxDynamicSharedMemorySize, SMEM_BYTES);

    prep_all<<<160 + BB, THREADS>>>(W1, W2, W3, q, b1, out);
    attn_mma2<<<NBLK, THREADS, SMEM_BYTES>>>(q, k, a1, a2, a3, Wl, bl, b2, b3, out);
}

// round 5
// speedup vs baseline: 3.0740x; 1.0827x over previous
#include <cuda_runtime.h>
#include <cuda_bf16.h>
#include <cstdint>

// ---------------- problem constants ----------------
#define BB 2048
#define TT 200
#define DD 64
#define H1 256
#define H2 128
#define H3 64
#define NTOK (BB * TT)
#define MTILE 128
#define NBLK (NTOK / MTILE)     // 3200
#define THREADS 512

// ---------------- smem layout (uint32 word offsets) ----------------
#define APITCH 68               // words per A-plane row (64 data + 4 pad)
#define BPITCH 20               // words per B-stage row (16 data + 4 pad)
#define BSTAGE_WORDS (128 * BPITCH)     // 2560
#define BSTAGE_PAIR  (2 * BSTAGE_WORDS) // hi+lo = 5120

#define OFF_A1H 0
#define OFF_A1L (OFF_A1H + 128 * APITCH)
#define OFF_A2H (OFF_A1L + 128 * APITCH)
#define OFF_A2L (OFF_A2H + 128 * APITCH)
#define OFF_BST (OFF_A2L + 128 * APITCH)      // 3 stages
#define OFF_QP  (OFF_BST + 3 * BSTAGE_PAIR)
#define OFF_K0  (OFF_QP + 512)
#define OFF_B2S (OFF_K0 + 128)
#define OFF_B3S (OFF_B2S + 128)
#define OFF_WL  (OFF_B3S + 64)
#define OFF_PART (OFF_WL + 64)                // part[128][4]
#define OFF_SC  (OFF_PART + 512)
#define SMEM_WORDS (OFF_SC + 128)
#define SMEM_BYTES (SMEM_WORDS * 4)           // ~206 KB

#define NCHUNK 20

// ---------------- device scratch ----------------
__device__ float g_qproj[BB * H1];
// [chunk 20][plane 2 (hi,lo)][n 128][kpair 16] uint32 = bf16x2(k even, k odd)
__device__ __align__(16) uint32_t g_Ball[NCHUNK * 4096];

// ---------------- helpers ----------------
__device__ __forceinline__ uint32_t smem_u32(const void* p) {
    uint32_t a;
    asm("{ .reg .u64 t; cvta.to.shared.u64 t, %1; cvt.u32.u64 %0, t; }"
        : "=r"(a) : "l"(p));
    return a;
}

__device__ __forceinline__ void split2(float x, float y, uint32_t& hi, uint32_t& lo) {
    __nv_bfloat16 xh = __float2bfloat16(x);
    __nv_bfloat16 yh = __float2bfloat16(y);
    __nv_bfloat16 xl = __float2bfloat16(x - __bfloat162float(xh));
    __nv_bfloat16 yl = __float2bfloat16(y - __bfloat162float(yh));
    __nv_bfloat162 h(xh, yh), l(xl, yl);
    hi = *reinterpret_cast<uint32_t*>(&h);
    lo = *reinterpret_cast<uint32_t*>(&l);
}

__device__ __forceinline__ void mma16816(float c[4], const uint32_t a[4],
                                         uint32_t b0, uint32_t b1) {
    asm volatile(
        "mma.sync.aligned.m16n8k16.row.col.f32.bf16.bf16.f32 "
        "{%0,%1,%2,%3},{%4,%5,%6,%7},{%8,%9},{%0,%1,%2,%3};"
        : "+f"(c[0]), "+f"(c[1]), "+f"(c[2]), "+f"(c[3])
        : "r"(a[0]), "r"(a[1]), "r"(a[2]), "r"(a[3]), "r"(b0), "r"(b1));
}

__device__ __forceinline__ void ldmat4(uint32_t r[4], uint32_t addr) {
    asm volatile("ldmatrix.sync.aligned.m8n8.x4.shared.b16 {%0,%1,%2,%3}, [%4];"
                 : "=r"(r[0]), "=r"(r[1]), "=r"(r[2]), "=r"(r[3]) : "r"(addr));
}

#define CP_ASYNC16(dst, src) \
    asm volatile("cp.async.cg.shared.global [%0], [%1], 16;" :: "r"(dst), "l"(src))
#define CP_COMMIT() asm volatile("cp.async.commit_group;" ::: "memory")
#define CP_WAIT1()  asm volatile("cp.async.wait_group 1;" ::: "memory")
#define CP_WAIT0()  asm volatile("cp.async.wait_group 0;" ::: "memory")

__device__ __forceinline__ void stage_issue(int nc, uint32_t smbase, int tid) {
    uint32_t dstbase = OFF_BST + (nc % 3) * BSTAGE_PAIR;
    const uint32_t* gsrc = g_Ball + nc * 4096;
#pragma unroll
    for (int j = 0; j < 2; j++) {
        int u = tid + j * THREADS;
        int plane = u >> 9, rem = u & 511, n = rem >> 2, seg = rem & 3;
        uint32_t dst = smbase + (dstbase + plane * BSTAGE_WORDS + n * BPITCH + seg * 4) * 4;
        CP_ASYNC16(dst, gsrc + plane * 2048 + n * 16 + seg * 4);
    }
}

__device__ __forceinline__ void chunk_pre(int seq, uint32_t smbase, int tid) {
    if (seq >= NCHUNK - 2) CP_WAIT0(); else CP_WAIT1();
    __syncthreads();
    if (seq + 2 < NCHUNK) {
        stage_issue(seq + 2, smbase, tid);
        CP_COMMIT();
    }
}

// one B-chunk (2 k16-steps) of 3-product MMAs. M32 x (NP*16) warp tile.
// acc flattened [2 ms][2*NP ns][4].
template <int NP>
__device__ __forceinline__ void chunk_mma(float (*acc)[4],
                                          uint32_t aH0, uint32_t aH1,
                                          uint32_t aL0, uint32_t aL1,
                                          uint32_t bH, uint32_t bL) {
    const int NS = 2 * NP;
#pragma unroll
    for (int sl = 0; sl < 2; sl++) {
        uint32_t A0h[4], A1h[4], A0l[4], A1l[4];
        ldmat4(A0h, aH0 + sl * 32);
        ldmat4(A1h, aH1 + sl * 32);
        ldmat4(A0l, aL0 + sl * 32);
        ldmat4(A1l, aL1 + sl * 32);
#pragma unroll
        for (int p = 0; p < NP; p++) {
            uint32_t bh[4], bl_[4];
            ldmat4(bh,  bH + p * 1280 + sl * 32);
            ldmat4(bl_, bL + p * 1280 + sl * 32);
            mma16816(acc[0 * NS + 2 * p],     A0h, bh[0],  bh[1]);
            mma16816(acc[0 * NS + 2 * p],     A0h, bl_[0], bl_[1]);
            mma16816(acc[0 * NS + 2 * p],     A0l, bh[0],  bh[1]);
            mma16816(acc[0 * NS + 2 * p + 1], A0h, bh[2],  bh[3]);
            mma16816(acc[0 * NS + 2 * p + 1], A0h, bl_[2], bl_[3]);
            mma16816(acc[0 * NS + 2 * p + 1], A0l, bh[2],  bh[3]);
            mma16816(acc[1 * NS + 2 * p],     A1h, bh[0],  bh[1]);
            mma16816(acc[1 * NS + 2 * p],     A1h, bl_[0], bl_[1]);
            mma16816(acc[1 * NS + 2 * p],     A1l, bh[0],  bh[1]);
            mma16816(acc[1 * NS + 2 * p + 1], A1h, bh[2],  bh[3]);
            mma16816(acc[1 * NS + 2 * p + 1], A1h, bl_[2], bl_[3]);
            mma16816(acc[1 * NS + 2 * p + 1], A1l, bh[2],  bh[3]);
        }
    }
}

// ---------------- merged prep kernel (weights + qproj + out zero) ----------
__global__ void prep_all(const float* __restrict__ W1,
                         const float* __restrict__ W2,
                         const float* __restrict__ W3,
                         const float* __restrict__ q,
                         const float* __restrict__ b1,
                         float* __restrict__ out) {
    int blk = blockIdx.x, tid = threadIdx.x;
    if (blk < 160) {
        int e = blk * 256 + tid;
        int c = e >> 11, rem = e & 2047, n = rem >> 4, kpl = rem & 15;
        float v0, v1;
        if (c < 4 || (c >= 8 && c < 12)) {       // B1
            int half = (c >= 8);
            int kp = (c & 3) * 16 + kpl;
            int ng = half * 128 + n;
            int k0i = 2 * kp, k1i = k0i + 1;
            v0 = (k0i < 64) ? (W1[(64 + k0i) * H1 + ng] - W1[(128 + k0i) * H1 + ng])
                            : W1[(128 + k0i) * H1 + ng];
            v1 = (k1i < 64) ? (W1[(64 + k1i) * H1 + ng] - W1[(128 + k1i) * H1 + ng])
                            : W1[(128 + k1i) * H1 + ng];
        } else if (c < 8) {                      // B2 kp 0..63
            int kp = (c - 4) * 16 + kpl;
            v0 = W2[(2 * kp) * H2 + n];
            v1 = W2[(2 * kp + 1) * H2 + n];
        } else if (c < 16) {                     // B2 kp 64..127
            int kp = 64 + (c - 12) * 16 + kpl;
            v0 = W2[(2 * kp) * H2 + n];
            v1 = W2[(2 * kp + 1) * H2 + n];
        } else {                                 // B3 (n padded to 128)
            int kp = (c - 16) * 16 + kpl;
            v0 = (n < 64) ? W3[(2 * kp) * H3 + n] : 0.f;
            v1 = (n < 64) ? W3[(2 * kp + 1) * H3 + n] : 0.f;
        }
        uint32_t hi, lo;
        split2(v0, v1, hi, lo);
        g_Ball[c * 4096 + n * 16 + kpl]        = hi;
        g_Ball[c * 4096 + 2048 + n * 16 + kpl] = lo;
    } else {
        int b = blk - 160;
        __shared__ float qs[DD];
        int n = tid;
        if (n < DD) qs[n] = q[b * DD + n];
        __syncthreads();
        float acc = b1[n];
#pragma unroll 8
        for (int i = 0; i < DD; i++)
            acc = fmaf(qs[i], W1[i * H1 + n] + W1[(2 * DD + i) * H1 + n], acc);
        g_qproj[b * H1 + n] = acc;
        if (n < 64) out[b * 64 + n] = 0.f;
    }
}

// ---------------- main fused kernel: 16 warps, M32xN32 tiles ----------------
__global__ void __launch_bounds__(THREADS, 1)
attn_mma3(const float* __restrict__ q,
          const float* __restrict__ kten,
          const float* __restrict__ a1,
          const float* __restrict__ a2,
          const float* __restrict__ a3,
          const float* __restrict__ Wl,
          const float* __restrict__ bl,
          const float* __restrict__ b2g,
          const float* __restrict__ b3g,
          float* __restrict__ out) {
    extern __shared__ uint32_t smw[];
    float* smf = (float*)smw;
    const uint32_t smbase = smem_u32(smw);

    const int tid  = threadIdx.x;
    const int w    = tid >> 5;
    const int lane = tid & 31;
    const int g    = lane >> 2;
    const int t    = lane & 3;
    const int T0   = blockIdx.x * MTILE;
    const int bA   = T0 / TT;
    const int bsplit = (bA + 1) * TT;
    const int bB   = (bA + 1 < BB) ? (bA + 1) : bA;
    const float blv = bl[0];

    const int mrow0 = (w & 3) * 32;      // 4 M-groups
    const int ngrp  = w >> 2;            // 4 N-groups
    const int ncol0 = ngrp * 32;         // layers 1 & 2
    const int ncol3 = ngrp * 16;         // layer 3

    // prologue: start chunks 0,1
    stage_issue(0, smbase, tid); CP_COMMIT();
    stage_issue(1, smbase, tid); CP_COMMIT();

    // ---- stage A1 planes (k: word cols 0..31, qk: 32..63), k0, qp, biases
    {
        int r = tid >> 2, qf = tid & 3;          // each thread: 16 cols of one row
        const float4* ksrc = (const float4*)(kten + (size_t)(T0 + r) * DD + qf * 16);
        int brow = (T0 + r) / TT;
        const float4* qsrc = (const float4*)(q + (size_t)brow * DD + qf * 16);
        uint32_t* a1h = smw + OFF_A1H + r * APITCH;
        uint32_t* a1l = smw + OFF_A1L + r * APITCH;
        uint32_t hi, lo;
#pragma unroll
        for (int i = 0; i < 4; i++) {
            float4 kk = ksrc[i];
            float4 qq = qsrc[i];
            int wc = qf * 8 + 2 * i;
            split2(kk.x, kk.y, hi, lo);
            a1h[wc] = hi; a1l[wc] = lo;
            split2(kk.z, kk.w, hi, lo);
            a1h[wc + 1] = hi; a1l[wc + 1] = lo;
            split2(kk.x * qq.x, kk.y * qq.y, hi, lo);
            a1h[32 + wc] = hi; a1l[32 + wc] = lo;
            split2(kk.z * qq.z, kk.w * qq.w, hi, lo);
            a1h[32 + wc + 1] = hi; a1l[32 + wc + 1] = lo;
            if (i == 0 && qf == 0) smf[OFF_K0 + r] = kk.x;
        }
        int bi = tid >> 8, c = tid & 255;
        smf[OFF_QP + tid] = g_qproj[(size_t)(bi ? bB : bA) * H1 + c];
        if (tid < 128) smf[OFF_B2S + tid] = b2g[tid];
        if (tid < 64)  smf[OFF_B3S + tid] = b3g[tid];
        if (tid >= 64 && tid < 128) smf[OFF_WL + tid - 64] = Wl[tid - 64];
    }

    // ---- precompute ldmatrix lane addresses
    const uint32_t a_lane = (((lane & 15) * APITCH) + ((lane >> 4) << 2)) * 4;
    const uint32_t aH1_0 = smbase + (OFF_A1H + mrow0 * APITCH) * 4 + a_lane;
    const uint32_t aH1_1 = aH1_0 + 16 * APITCH * 4;
    const uint32_t aL1_0 = aH1_0 + (OFF_A1L - OFF_A1H) * 4;
    const uint32_t aL1_1 = aH1_1 + (OFF_A1L - OFF_A1H) * 4;
    const uint32_t aH2_0 = smbase + (OFF_A2H + mrow0 * APITCH) * 4 + a_lane;
    const uint32_t aH2_1 = aH2_0 + 16 * APITCH * 4;
    const uint32_t aL2_0 = aH2_0 + (OFF_A2L - OFF_A2H) * 4;
    const uint32_t aL2_1 = aH2_1 + (OFF_A2L - OFF_A2H) * 4;
    const uint32_t b_lane =
        ((((lane & 7) + ((lane >> 4) << 3)) * BPITCH) + (((lane >> 3) & 1) << 2)) * 4;
    const uint32_t bwarp12 = ncol0 * BPITCH * 4 + b_lane;
    const uint32_t bwarp3  = ncol3 * BPITCH * 4 + b_lane;

    float acc2[8][4];
#pragma unroll
    for (int i = 0; i < 8; i++)
#pragma unroll
        for (int e = 0; e < 4; e++) acc2[i][e] = 0.f;

    int seq = 0;
#pragma unroll 1
    for (int h = 0; h < 2; h++) {
        // ===== layer 1 (half h): D1 cols [h*128, h*128+128)
        float acc1[8][4];
#pragma unroll
        for (int i = 0; i < 8; i++)
#pragma unroll
            for (int e = 0; e < 4; e++) acc1[i][e] = 0.f;

#pragma unroll 1
        for (int kc = 0; kc < 4; kc++) {
            chunk_pre(seq, smbase, tid);
            uint32_t bufb = smbase + (OFF_BST + (seq % 3) * BSTAGE_PAIR) * 4;
            uint32_t bH = bufb + bwarp12;
            uint32_t bL = bH + BSTAGE_WORDS * 4;
            uint32_t wb = kc * 64;
            chunk_mma<2>(acc1, aH1_0 + wb, aH1_1 + wb, aL1_0 + wb, aL1_1 + wb, bH, bL);
            seq++;
        }

        // epilogue 1 -> A2 chunk planes (local word cols 0..63)
#pragma unroll
        for (int ms = 0; ms < 2; ms++)
#pragma unroll
            for (int ro = 0; ro < 2; ro++) {
                int r = mrow0 + ms * 16 + ro * 8 + g;
                int tok = T0 + r;
                int bt = tok >= bsplit;
                int tt = tok - (bt ? bsplit : bA * TT);
                const float* a1row = a1 + (size_t)tt * H1;
#pragma unroll
                for (int ns = 0; ns < 4; ns++) {
                    int gcol = h * 128 + ncol0 + ns * 8 + 2 * t;
                    float v0 = acc1[ms * 4 + ns][ro * 2]     + smf[OFF_QP + bt * 256 + gcol];
                    float v1 = acc1[ms * 4 + ns][ro * 2 + 1] + smf[OFF_QP + bt * 256 + gcol + 1];
                    float2 av = *(const float2*)&a1row[gcol];
                    v0 = v0 > 0.f ? v0 : v0 * av.x;
                    v1 = v1 > 0.f ? v1 : v1 * av.y;
                    uint32_t hi, lo;
                    split2(v0, v1, hi, lo);
                    int wc = ngrp * 16 + ns * 4 + t;
                    smw[OFF_A2H + r * APITCH + wc] = hi;
                    smw[OFF_A2L + r * APITCH + wc] = lo;
                }
            }

        // ===== layer 2 partial: K cols [h*128, h*128+128) accumulate
#pragma unroll 1
        for (int kc = 0; kc < 4; kc++) {
            chunk_pre(seq, smbase, tid);   // barrier also publishes A2 writes
            uint32_t bufb = smbase + (OFF_BST + (seq % 3) * BSTAGE_PAIR) * 4;
            uint32_t bH = bufb + bwarp12;
            uint32_t bL = bH + BSTAGE_WORDS * 4;
            uint32_t wb = kc * 64;
            chunk_mma<2>(acc2, aH2_0 + wb, aH2_1 + wb, aL2_0 + wb, aL2_1 + wb, bH, bL);
            seq++;
        }
    }

    // ===== layer 2 epilogue -> A3 planes (reuse A2 buffers)
    __syncthreads();
#pragma unroll
    for (int ms = 0; ms < 2; ms++)
#pragma unroll
        for (int ro = 0; ro < 2; ro++) {
            int r = mrow0 + ms * 16 + ro * 8 + g;
            int tok = T0 + r;
            int bt = tok >= bsplit;
            int tt = tok - (bt ? bsplit : bA * TT);
            const float* a2row = a2 + (size_t)tt * H2;
#pragma unroll
            for (int ns = 0; ns < 4; ns++) {
                int col = ncol0 + ns * 8 + 2 * t;
                float v0 = acc2[ms * 4 + ns][ro * 2]     + smf[OFF_B2S + col];
                float v1 = acc2[ms * 4 + ns][ro * 2 + 1] + smf[OFF_B2S + col + 1];
                float2 av = *(const float2*)&a2row[col];
                v0 = v0 > 0.f ? v0 : v0 * av.x;
                v1 = v1 > 0.f ? v1 : v1 * av.y;
                uint32_t hi, lo;
                split2(v0, v1, hi, lo);
                int wc = ngrp * 16 + ns * 4 + t;
                smw[OFF_A2H + r * APITCH + wc] = hi;
                smw[OFF_A2L + r * APITCH + wc] = lo;
            }
        }

    // ===== layer 3
    float acc3[4][4];
#pragma unroll
    for (int i = 0; i < 4; i++)
#pragma unroll
        for (int e = 0; e < 4; e++) acc3[i][e] = 0.f;

#pragma unroll 1
    for (int kc = 0; kc < 4; kc++) {
        chunk_pre(seq, smbase, tid);
        uint32_t bufb = smbase + (OFF_BST + (seq % 3) * BSTAGE_PAIR) * 4;
        uint32_t bH = bufb + bwarp3;
        uint32_t bL = bH + BSTAGE_WORDS * 4;
        uint32_t wb = kc * 64;
        chunk_mma<1>(acc3, aH2_0 + wb, aH2_1 + wb, aL2_0 + wb, aL2_1 + wb, bH, bL);
        seq++;
    }

    // epilogue 3: PReLU + dot(Wl) -> per-row partials
#pragma unroll
    for (int ms = 0; ms < 2; ms++)
#pragma unroll
        for (int ro = 0; ro < 2; ro++) {
            int r = mrow0 + ms * 16 + ro * 8 + g;
            int tok = T0 + r;
            int bt = tok >= bsplit;
            int tt = tok - (bt ? bsplit : bA * TT);
            const float* a3row = a3 + (size_t)tt * H3;
            float rp = 0.f;
#pragma unroll
            for (int ns = 0; ns < 2; ns++) {
                int col = ncol3 + ns * 8 + 2 * t;
                float v0 = acc3[ms * 2 + ns][ro * 2]     + smf[OFF_B3S + col];
                float v1 = acc3[ms * 2 + ns][ro * 2 + 1] + smf[OFF_B3S + col + 1];
                float2 av = *(const float2*)&a3row[col];
                v0 = v0 > 0.f ? v0 : v0 * av.x;
                v1 = v1 > 0.f ? v1 : v1 * av.y;
                rp = fmaf(v0, smf[OFF_WL + col], rp);
                rp = fmaf(v1, smf[OFF_WL + col + 1], rp);
            }
            rp += __shfl_xor_sync(0xFFFFFFFFu, rp, 1);
            rp += __shfl_xor_sync(0xFFFFFFFFu, rp, 2);
            if (t == 0) smf[OFF_PART + r * 4 + ngrp] = rp;
        }
    __syncthreads();

    if (tid < 128) {
        float sc = smf[OFF_PART + tid * 4] + smf[OFF_PART + tid * 4 + 1]
                 + smf[OFF_PART + tid * 4 + 2] + smf[OFF_PART + tid * 4 + 3] + blv;
        smf[OFF_SC + tid] = (smf[OFF_K0 + tid] != 0.f) ? sc : 0.f;
    }
    __syncthreads();

    // ---- pooling: warp w handles rows [w*8, w*8+8); k from A1 planes
    {
        int r0 = w * 8;
        int bF = (T0 + r0) / TT;
        int bL2 = (T0 + r0 + 7) / TT;
        float s0a = 0.f, s0b = 0.f, s1a = 0.f, s1b = 0.f;
#pragma unroll
        for (int j = 0; j < 8; j++) {
            int r = r0 + j;
            float s = smf[OFF_SC + r];
            uint32_t wh0 = smw[OFF_A1H + r * APITCH + (lane >> 1)];
            uint32_t wl0 = smw[OFF_A1L + r * APITCH + (lane >> 1)];
            uint32_t wh1 = smw[OFF_A1H + r * APITCH + 16 + (lane >> 1)];
            uint32_t wl1 = smw[OFF_A1L + r * APITCH + 16 + (lane >> 1)];
            __nv_bfloat162 h0 = *reinterpret_cast<__nv_bfloat162*>(&wh0);
            __nv_bfloat162 l0 = *reinterpret_cast<__nv_bfloat162*>(&wl0);
            __nv_bfloat162 h1 = *reinterpret_cast<__nv_bfloat162*>(&wh1);
            __nv_bfloat162 l1 = *reinterpret_cast<__nv_bfloat162*>(&wl1);
            float kv0 = (lane & 1) ? (__bfloat162float(h0.y) + __bfloat162float(l0.y))
                                   : (__bfloat162float(h0.x) + __bfloat162float(l0.x));
            float kv1 = (lane & 1) ? (__bfloat162float(h1.y) + __bfloat162float(l1.y))
                                   : (__bfloat162float(h1.x) + __bfloat162float(l1.x));
            if ((T0 + r) / TT == bF) { s0a = fmaf(s, kv0, s0a); s0b = fmaf(s, kv1, s0b); }
            else                     { s1a = fmaf(s, kv0, s1a); s1b = fmaf(s, kv1, s1b); }
        }
        atomicAdd(&out[bF * DD + lane],      s0a);
        atomicAdd(&out[bF * DD + 32 + lane], s0b);
        if (bL2 != bF) {
            atomicAdd(&out[bL2 * DD + lane],      s1a);
            atomicAdd(&out[bL2 * DD + 32 + lane], s1b);
        }
    }
}

// ---------------------------------------------------------------------------
extern "C" void kernel_launch(void* const* d_in, const int* in_sizes, int n_in,
                              void* d_out, int out_size) {
    const float* q  = (const float*)d_in[0];
    const float* k  = (const float*)d_in[1];
    const float* W1 = (const float*)d_in[2];
    const float* b1 = (const float*)d_in[3];
    const float* a1 = (const float*)d_in[4];
    const float* W2 = (const float*)d_in[5];
    const float* b2 = (const float*)d_in[6];
    const float* a2 = (const float*)d_in[7];
    const float* W3 = (const float*)d_in[8];
    const float* b3 = (const float*)d_in[9];
    const float* a3 = (const float*)d_in[10];
    const float* Wl = (const float*)d_in[11];
    const float* bl = (const float*)d_in[12];
    float* out = (float*)d_out;

    cudaFuncSetAttribute(attn_mma3,
                         cudaFuncAttributeMaxDynamicSharedMemorySize, SMEM_BYTES);

    prep_all<<<160 + BB, 256>>>(W1, W2, W3, q, b1, out);
    attn_mma3<<<NBLK, THREADS, SMEM_BYTES>>>(q, k, a1, a2, a3, Wl, bl, b2, b3, out);
}